// round 12
// baseline (speedup 1.0000x reference)
#include <cuda_runtime.h>

#define THREADS 256
#define ROWS    64

// Prep block layout (floats) — identical in gPrep and shared memory:
#define OFF_WT   0        // 64 x 64  Wt[k][i]
#define OFF_GT   4096     // 64 x 64  Gt[k][i]
#define OFF_M    8192     // 64 x 64  M[k][l]
#define OFF_B    12288
#define OFF_WY   12352
#define OFF_wy   12416
#define OFF_wlt  12480
#define OFF_wys  12544
#define OFF_MISC 12608    // [0]=wl[64]
#define PREP_FLOATS 12624

// shared-only extras
#define OFF_RED  12624    // 8 warps x 2
#define OFF_PART 12640    // 7 partner warps x 4 vals x 64 rows = 1792
#define OFF_FLAG 14432
#define OFF_X    14436    // input stage, 64 x 65 (stride 65 -> conflict-free)
#define OFF_S    18596    // s values,    64 x 65
#define SMEM_FLOATS 22756
#define SMEM_BYTES  (SMEM_FLOATS * 4)

// ---- persistent device scratch ----
__device__ float        gPrep[PREP_FLOATS];
__device__ float        gPartI[512];
__device__ float        gPartN[512];
__device__ unsigned int gCount = 0;

__device__ __forceinline__ int pair_off(int i) {
    return 129 + i * (2 * 129 - i - 1) / 2;
}
__device__ __forceinline__ unsigned long long packpair(float a, float b) {
    unsigned long long r;
    asm("mov.b64 %0, {%1, %2};" : "=l"(r) : "f"(a), "f"(b));
    return r;
}
__device__ __forceinline__ void unpack2(unsigned long long v, float& a, float& b) {
    asm("mov.b64 {%0, %1}, %2;" : "=f"(a), "=f"(b) : "l"(v));
}
#define FMA2(acc, a, b) asm("fma.rn.f32x2 %0, %1, %2, %0;" : "+l"(acc) : "l"(a), "l"(b))

__device__ __forceinline__ float red2(unsigned long long v) {
    float a, b;
    unpack2(v, a, b);
    return a + b;
}

__device__ __forceinline__ float tanh_fast(float w) {
    float e, r;
    asm("ex2.approx.f32 %0, %1;" : "=f"(e) : "f"(w * 2.885390081777927f));
    asm("rcp.approx.f32 %0, %1;" : "=f"(r) : "f"(e + 1.0f));
    return fmaf(-2.0f, r, 1.0f);
}

// ---------------------------------------------------------------------------
__global__ void prep_kernel(const float* __restrict__ tw,
                            const float* __restrict__ tb,
                            const float* __restrict__ mw) {
    int tid = blockIdx.x * blockDim.x + threadIdx.x;
    if (tid >= PREP_FLOATS) return;
    float v = 0.0f;
    if (tid < 4096) {                       // Wt[k][i]
        int k = tid >> 6, i = tid & 63;
        v = tw[k * 65 + i];
    } else if (tid < 8192) {                // Gt[k][i]
        int idx = tid - 4096;
        int k = idx >> 6, i = idx & 63;
        v = mw[pair_off(i) + 64 + k - i];
    } else if (tid < 12288) {               // M[k][l]
        int idx = tid - 8192;
        int k = idx >> 6, l = idx & 63;
        if (k != l) {
            int a = k < l ? k : l;
            int b = k < l ? l : k;
            v = 0.5f * mw[pair_off(65 + a) + b - a - 1];
        }
    } else if (tid < 12352) {
        v = tb[tid - 12288];
    } else if (tid < 12416) {
        int k = tid - 12352;
        v = tw[k * 65 + 64];
    } else if (tid < 12480) {
        int i = tid - 12416;
        v = mw[pair_off(i) + 63 - i];
    } else if (tid < 12544) {
        v = mw[65 + (tid - 12480)];
    } else if (tid < 12608) {
        v = mw[pair_off(64) + (tid - 12544)];
    } else if (tid == 12608) {
        v = mw[64];
    }
    gPrep[tid] = v;
    if (tid == 0) gCount = 0;
}

// ---------------------------------------------------------------------------
// 256 threads: warp = k-eighth (8 k's, warp-uniform weight reads),
// lane = row-pair (rows lane, lane+32). x/s staged in quarters so peak
// register demand stays ~100 (< 128 cap at 2 blocks/SM) -> no spills.
// ---------------------------------------------------------------------------
__global__ void __launch_bounds__(THREADS, 2)
fused_kernel(const float* __restrict__ inps,
             float* __restrict__ out,
             int Bn) {
    extern __shared__ float sm[];
    const int t    = threadIdx.x;
    const int lane = t & 31;
    const int q    = t >> 5;          // warp = k-eighth, 0..7
    const int kb   = q * 8;
    const int rA   = lane;
    const int rB   = lane + 32;
    const int row0 = blockIdx.x * ROWS;

    // coalesced weight copy
    {
        const float4* src = reinterpret_cast<const float4*>(gPrep);
        float4* dst = reinterpret_cast<float4*>(sm);
        for (int idx = t; idx < PREP_FLOATS / 4; idx += THREADS)
            dst[idx] = src[idx];
    }
    // coalesced input stage
    {
        const float4* src = reinterpret_cast<const float4*>(inps + (long)row0 * 65);
        float4* dst = reinterpret_cast<float4*>(sm + OFF_X);
        for (int idx = t; idx < (ROWS * 65) / 4; idx += THREADS)
            dst[idx] = src[idx];
    }
    __syncthreads();

    const float* XA = sm + OFF_X + rA * 65;
    const float* XB = sm + OFF_X + rB * 65;
    float* SA = sm + OFF_S + rA * 65;
    float* SB = sm + OFF_S + rB * 65;
    const float yA = XA[64];
    const float yB = XB[64];

    // x . wy over this warp's 8 i's (combined across warps later)
    float xwA = 0.0f, xwB = 0.0f;
#pragma unroll
    for (int j = 0; j < 8; j++) {
        float w = sm[OFF_wy + kb + j];
        xwA = fmaf(XA[kb + j], w, xwA);
        xwB = fmaf(XB[kb + j], w, xwB);
    }

    // ---- Phase 1: c = x.Wt, a = x.Gt over this warp's 8 k's ----
    float cvA[8], cvB[8], avA[8], avB[8];
#pragma unroll
    for (int kk = 0; kk < 8; kk++) { cvA[kk] = 0.0f; cvB[kk] = 0.0f; avA[kk] = 0.0f; avB[kk] = 0.0f; }

#pragma unroll
    for (int qt = 0; qt < 4; qt++) {
        unsigned long long xa[8], xb[8];
#pragma unroll
        for (int j = 0; j < 8; j++) {
            xa[j] = packpair(XA[qt * 16 + 2 * j], XA[qt * 16 + 2 * j + 1]);
            xb[j] = packpair(XB[qt * 16 + 2 * j], XB[qt * 16 + 2 * j + 1]);
        }
#pragma unroll
        for (int kk = 0; kk < 8; kk++) {
            int k = kb + kk;
            const ulonglong2* pW = reinterpret_cast<const ulonglong2*>(sm + OFF_WT + k * 64 + qt * 16);
            const ulonglong2* pG = reinterpret_cast<const ulonglong2*>(sm + OFF_GT + k * 64 + qt * 16);
            ulonglong2 W0 = pW[0], W1 = pW[1], W2 = pW[2], W3 = pW[3];
            ulonglong2 G0 = pG[0], G1 = pG[1], G2 = pG[2], G3 = pG[3];
            unsigned long long cA = 0ULL, cB = 0ULL, aA = 0ULL, aB = 0ULL;
            FMA2(cA, xa[0], W0.x); FMA2(cA, xa[1], W0.y);
            FMA2(cA, xa[2], W1.x); FMA2(cA, xa[3], W1.y);
            FMA2(cA, xa[4], W2.x); FMA2(cA, xa[5], W2.y);
            FMA2(cA, xa[6], W3.x); FMA2(cA, xa[7], W3.y);
            FMA2(cB, xb[0], W0.x); FMA2(cB, xb[1], W0.y);
            FMA2(cB, xb[2], W1.x); FMA2(cB, xb[3], W1.y);
            FMA2(cB, xb[4], W2.x); FMA2(cB, xb[5], W2.y);
            FMA2(cB, xb[6], W3.x); FMA2(cB, xb[7], W3.y);
            FMA2(aA, xa[0], G0.x); FMA2(aA, xa[1], G0.y);
            FMA2(aA, xa[2], G1.x); FMA2(aA, xa[3], G1.y);
            FMA2(aA, xa[4], G2.x); FMA2(aA, xa[5], G2.y);
            FMA2(aA, xa[6], G3.x); FMA2(aA, xa[7], G3.y);
            FMA2(aB, xb[0], G0.x); FMA2(aB, xb[1], G0.y);
            FMA2(aB, xb[2], G1.x); FMA2(aB, xb[3], G1.y);
            FMA2(aB, xb[4], G2.x); FMA2(aB, xb[5], G2.y);
            FMA2(aB, xb[6], G3.x); FMA2(aB, xb[7], G3.y);
            cvA[kk] += red2(cA);
            cvB[kk] += red2(cB);
            avA[kk] += red2(aA);
            avB[kk] += red2(aB);
        }
    }

    // ---- epilogue: tanh, d/s, penalties, gz += d.a ----
    float dA[8], dB[8];
    float dwA = 0.0f, dwB = 0.0f, swA = 0.0f, swB = 0.0f;
    float gzA = 0.0f, gzB = 0.0f, accI = 0.0f, accN = 0.0f;
#pragma unroll
    for (int kk = 0; kk < 8; kk++) {
        int k = kb + kk;
        float bk  = sm[OFF_B + k];
        float wyk = sm[OFF_WY + k];
        float wlt = sm[OFF_wlt + k];
        float wys = sm[OFF_wys + k];

        float cv = cvA[kk] + bk;
        float hv = yA * wyk;
        float w1 = cv + hv, w2 = cv - hv;
        float t1 = tanh_fast(w1), t2 = tanh_fast(w2);
        float dk = t1 - t2, sk = t1 + t2;
        dA[kk] = dk;
        SA[k]  = sk;
        gzA = fmaf(dk, avA[kk], gzA);
        dwA = fmaf(dk, wlt, dwA);
        swA = fmaf(sk, wys, swA);
        float e1 = fmaf(-t1, t1, 1.0f), e2 = fmaf(-t2, t2, 1.0f);
        accI = fmaf(e1, e1, accI);
        accI = fmaf(e2, e2, accI);
        float nt = fmaf(t2, w2, -(t1 * w1));
        accN = fmaf(nt, nt, accN);

        cv = cvB[kk] + bk;
        hv = yB * wyk;
        w1 = cv + hv; w2 = cv - hv;
        t1 = tanh_fast(w1); t2 = tanh_fast(w2);
        dk = t1 - t2; sk = t1 + t2;
        dB[kk] = dk;
        SB[k]  = sk;
        gzB = fmaf(dk, avB[kk], gzB);
        dwB = fmaf(dk, wlt, dwB);
        swB = fmaf(sk, wys, swB);
        e1 = fmaf(-t1, t1, 1.0f); e2 = fmaf(-t2, t2, 1.0f);
        accI = fmaf(e1, e1, accI);
        accI = fmaf(e2, e2, accI);
        nt = fmaf(t2, w2, -(t1 * w1));
        accN = fmaf(nt, nt, accN);
    }

    __syncthreads();   // all s written

    // ---- Phase 2: gz += d^T M s (s staged per quarter) ----
    float mvA[8], mvB[8];
#pragma unroll
    for (int kk = 0; kk < 8; kk++) { mvA[kk] = 0.0f; mvB[kk] = 0.0f; }

#pragma unroll
    for (int qt = 0; qt < 4; qt++) {
        unsigned long long sa[8], sb[8];
#pragma unroll
        for (int j = 0; j < 8; j++) {
            sa[j] = packpair(SA[qt * 16 + 2 * j], SA[qt * 16 + 2 * j + 1]);
            sb[j] = packpair(SB[qt * 16 + 2 * j], SB[qt * 16 + 2 * j + 1]);
        }
#pragma unroll
        for (int kk = 0; kk < 8; kk++) {
            int k = kb + kk;
            const ulonglong2* pM = reinterpret_cast<const ulonglong2*>(sm + OFF_M + k * 64 + qt * 16);
            ulonglong2 M0 = pM[0], M1 = pM[1], M2 = pM[2], M3 = pM[3];
            unsigned long long mA = 0ULL, mB = 0ULL;
            FMA2(mA, sa[0], M0.x); FMA2(mA, sa[1], M0.y);
            FMA2(mA, sa[2], M1.x); FMA2(mA, sa[3], M1.y);
            FMA2(mA, sa[4], M2.x); FMA2(mA, sa[5], M2.y);
            FMA2(mA, sa[6], M3.x); FMA2(mA, sa[7], M3.y);
            FMA2(mB, sb[0], M0.x); FMA2(mB, sb[1], M0.y);
            FMA2(mB, sb[2], M1.x); FMA2(mB, sb[3], M1.y);
            FMA2(mB, sb[4], M2.x); FMA2(mB, sb[5], M2.y);
            FMA2(mB, sb[6], M3.x); FMA2(mB, sb[7], M3.y);
            mvA[kk] += red2(mA);
            mvB[kk] += red2(mB);
        }
    }
#pragma unroll
    for (int kk = 0; kk < 8; kk++) {
        gzA = fmaf(dA[kk], mvA[kk], gzA);
        gzB = fmaf(dB[kk], mvB[kk], gzB);
    }

    // ---- combine the 8 k-eighth warps ----
    if (q != 0) {
        int p = OFF_PART + (q - 1) * 256;
        sm[p + rA]       = gzA;  sm[p + rB]       = gzB;
        sm[p + 64 + rA]  = dwA;  sm[p + 64 + rB]  = dwB;
        sm[p + 128 + rA] = swA;  sm[p + 128 + rB] = swB;
        sm[p + 192 + rA] = xwA;  sm[p + 192 + rB] = xwB;
    }
    __syncthreads();
    if (q == 0) {
#pragma unroll
        for (int p = 0; p < 7; p++) {
            int b = OFF_PART + p * 256;
            gzA += sm[b + rA];       gzB += sm[b + rB];
            dwA += sm[b + 64 + rA];  dwB += sm[b + 64 + rB];
            swA += sm[b + 128 + rA]; swB += sm[b + 128 + rB];
            xwA += sm[b + 192 + rA]; xwB += sm[b + 192 + rB];
        }
        float wl64 = sm[OFF_MISC];
        out[row0 + rA] = 1.0f + 2.0f * yA * wl64 + dwA + 2.0f * yA * xwA + yA * swA + gzA;
        out[row0 + rB] = 1.0f + 2.0f * yB * wl64 + dwB + 2.0f * yB * xwB + yB * swB + gzB;
    }

    // ---- penalty reduction ----
#pragma unroll
    for (int off = 16; off > 0; off >>= 1) {
        accI += __shfl_xor_sync(0xffffffffu, accI, off);
        accN += __shfl_xor_sync(0xffffffffu, accN, off);
    }
    if (lane == 0) {
        sm[OFF_RED + q]     = accI;
        sm[OFF_RED + 8 + q] = accN;
    }
    __syncthreads();
    if (t == 0) {
        float pI = 0.0f, pN = 0.0f;
#pragma unroll
        for (int w = 0; w < 8; w++) { pI += sm[OFF_RED + w]; pN += sm[OFF_RED + 8 + w]; }
        gPartI[blockIdx.x] = pI;
        gPartN[blockIdx.x] = pN;
        __threadfence();
        unsigned int tk = atomicAdd(&gCount, 1u);
        sm[OFF_FLAG] = (tk == gridDim.x - 1) ? 1.0f : 0.0f;
    }
    __syncthreads();

    if (sm[OFF_FLAG] != 0.0f && t < 32) {
        __threadfence();
        double sI = 0.0, sN = 0.0;
        for (int i = t; i < (int)gridDim.x; i += 32) {
            sI += (double)gPartI[i];
            sN += (double)gPartN[i];
        }
#pragma unroll
        for (int off = 16; off > 0; off >>= 1) {
            sI += __shfl_xor_sync(0xffffffffu, sI, off);
            sN += __shfl_xor_sync(0xffffffffu, sN, off);
        }
        if (t == 0) {
            out[Bn]     = (float)(sI * (1.0 / 300.0));
            out[Bn + 1] = (float)sN;
            gCount = 0;   // reset for next graph replay
        }
    }
}

extern "C" void kernel_launch(void* const* d_in, const int* in_sizes, int n_in,
                              void* d_out, int out_size) {
    const float* inps = (const float*)d_in[0];
    const float* tw   = (const float*)d_in[1];
    const float* tb   = (const float*)d_in[2];
    const float* mw   = (const float*)d_in[3];
    float* out = (float*)d_out;

    int Bn = in_sizes[0] / 65;

    cudaFuncSetAttribute(fused_kernel,
                         cudaFuncAttributeMaxDynamicSharedMemorySize, SMEM_BYTES);

    prep_kernel<<<(PREP_FLOATS + 255) / 256, 256>>>(tw, tb, mw);
    fused_kernel<<<Bn / ROWS, THREADS, SMEM_BYTES>>>(inps, out, Bn);
}

// round 14
// speedup vs baseline: 1.4287x; 1.4287x over previous
#include <cuda_runtime.h>

#define THREADS 256
#define ROWS    64

// Prep block layout (floats) — identical in gPrep and shared memory:
#define OFF_WT   0        // 64 x 64  Wt[k][i]
#define OFF_GT   4096     // 64 x 64  Gt[k][i]
#define OFF_M    8192     // 64 x 64  M[k][l]
#define OFF_B    12288
#define OFF_WY   12352
#define OFF_wy   12416
#define OFF_wlt  12480
#define OFF_wys  12544
#define OFF_MISC 12608    // [0]=wl[64]
#define PREP_FLOATS 12624

// shared-only extras
#define OFF_RED  12624    // 8 warps x 2
#define OFF_PART 12640    // 7 partner warps x 4 vals x 64 rows = 1792
#define OFF_FLAG 14432
#define OFF_X    14436    // input stage, 64 x 65 (stride 65 -> conflict-free)
#define OFF_S    18596    // s values,    64 x 65
#define SMEM_FLOATS 22756
#define SMEM_BYTES  (SMEM_FLOATS * 4)

// ---- persistent device scratch ----
__device__ float        gPrep[PREP_FLOATS];
__device__ float        gPartI[512];
__device__ float        gPartN[512];
__device__ unsigned int gCount = 0;

__device__ __forceinline__ int pair_off(int i) {
    return 129 + i * (2 * 129 - i - 1) / 2;
}
__device__ __forceinline__ unsigned long long packpair(float a, float b) {
    unsigned long long r;
    asm("mov.b64 %0, {%1, %2};" : "=l"(r) : "f"(a), "f"(b));
    return r;
}
__device__ __forceinline__ void unpack2(unsigned long long v, float& a, float& b) {
    asm("mov.b64 {%0, %1}, %2;" : "=f"(a), "=f"(b) : "l"(v));
}
#define FMA2(acc, a, b) asm("fma.rn.f32x2 %0, %1, %2, %0;" : "+l"(acc) : "l"(a), "l"(b))

__device__ __forceinline__ float red2(unsigned long long v) {
    float a, b;
    unpack2(v, a, b);
    return a + b;
}

__device__ __forceinline__ float tanh_fast(float w) {
    float e, r;
    asm("ex2.approx.f32 %0, %1;" : "=f"(e) : "f"(w * 2.885390081777927f));
    asm("rcp.approx.f32 %0, %1;" : "=f"(r) : "f"(e + 1.0f));
    return fmaf(-2.0f, r, 1.0f);
}

// ---------------------------------------------------------------------------
__global__ void prep_kernel(const float* __restrict__ tw,
                            const float* __restrict__ tb,
                            const float* __restrict__ mw) {
    int tid = blockIdx.x * blockDim.x + threadIdx.x;
    if (tid >= PREP_FLOATS) return;
    float v = 0.0f;
    if (tid < 4096) {                       // Wt[k][i]
        int k = tid >> 6, i = tid & 63;
        v = tw[k * 65 + i];
    } else if (tid < 8192) {                // Gt[k][i]
        int idx = tid - 4096;
        int k = idx >> 6, i = idx & 63;
        v = mw[pair_off(i) + 64 + k - i];
    } else if (tid < 12288) {               // M[k][l]
        int idx = tid - 8192;
        int k = idx >> 6, l = idx & 63;
        if (k != l) {
            int a = k < l ? k : l;
            int b = k < l ? l : k;
            v = 0.5f * mw[pair_off(65 + a) + b - a - 1];
        }
    } else if (tid < 12352) {
        v = tb[tid - 12288];
    } else if (tid < 12416) {
        int k = tid - 12352;
        v = tw[k * 65 + 64];
    } else if (tid < 12480) {
        int i = tid - 12416;
        v = mw[pair_off(i) + 63 - i];
    } else if (tid < 12544) {
        v = mw[65 + (tid - 12480)];
    } else if (tid < 12608) {
        v = mw[pair_off(64) + (tid - 12544)];
    } else if (tid == 12608) {
        v = mw[64];
    }
    gPrep[tid] = v;
    if (tid == 0) gCount = 0;
}

// ---------------------------------------------------------------------------
// 256 threads: warp = k-eighth (8 k's, warp-uniform weight reads),
// lane = row-pair (rows lane, lane+32). Packed f32x2 accumulators persist
// across the whole i-loop; horizontal reduce happens ONCE per k.
// ---------------------------------------------------------------------------
__global__ void __launch_bounds__(THREADS, 2)
fused_kernel(const float* __restrict__ inps,
             float* __restrict__ out,
             int Bn) {
    extern __shared__ float sm[];
    const int t    = threadIdx.x;
    const int lane = t & 31;
    const int q    = t >> 5;          // warp = k-eighth, 0..7
    const int kb   = q * 8;
    const int rA   = lane;
    const int rB   = lane + 32;
    const int row0 = blockIdx.x * ROWS;

    // coalesced weight copy
    {
        const float4* src = reinterpret_cast<const float4*>(gPrep);
        float4* dst = reinterpret_cast<float4*>(sm);
        for (int idx = t; idx < PREP_FLOATS / 4; idx += THREADS)
            dst[idx] = src[idx];
    }
    // coalesced input stage
    {
        const float4* src = reinterpret_cast<const float4*>(inps + (long)row0 * 65);
        float4* dst = reinterpret_cast<float4*>(sm + OFF_X);
        for (int idx = t; idx < (ROWS * 65) / 4; idx += THREADS)
            dst[idx] = src[idx];
    }
    __syncthreads();

    const float* XA = sm + OFF_X + rA * 65;
    const float* XB = sm + OFF_X + rB * 65;
    float* SA = sm + OFF_S + rA * 65;
    float* SB = sm + OFF_S + rB * 65;
    const float yA = XA[64];
    const float yB = XB[64];

    // x . wy over this warp's 8 i's (combined across warps later)
    float xwA = 0.0f, xwB = 0.0f;
#pragma unroll
    for (int j = 0; j < 8; j++) {
        float w = sm[OFF_wy + kb + j];
        xwA = fmaf(XA[kb + j], w, xwA);
        xwB = fmaf(XB[kb + j], w, xwB);
    }

    // ---- Phase 1: c = x.Wt, a = x.Gt — persistent packed accumulators ----
    unsigned long long cA[8], cB[8], aA[8], aB[8];
#pragma unroll
    for (int kk = 0; kk < 8; kk++) { cA[kk] = 0ULL; cB[kk] = 0ULL; aA[kk] = 0ULL; aB[kk] = 0ULL; }

#pragma unroll
    for (int qt = 0; qt < 4; qt++) {
        unsigned long long xa[8], xb[8];
#pragma unroll
        for (int j = 0; j < 8; j++) {
            xa[j] = packpair(XA[qt * 16 + 2 * j], XA[qt * 16 + 2 * j + 1]);
            xb[j] = packpair(XB[qt * 16 + 2 * j], XB[qt * 16 + 2 * j + 1]);
        }
#pragma unroll
        for (int kk = 0; kk < 8; kk++) {
            int k = kb + kk;
            const ulonglong2* pW = reinterpret_cast<const ulonglong2*>(sm + OFF_WT + k * 64 + qt * 16);
            const ulonglong2* pG = reinterpret_cast<const ulonglong2*>(sm + OFF_GT + k * 64 + qt * 16);
            ulonglong2 W0 = pW[0], W1 = pW[1], W2 = pW[2], W3 = pW[3];
            ulonglong2 G0 = pG[0], G1 = pG[1], G2 = pG[2], G3 = pG[3];
            FMA2(cA[kk], xa[0], W0.x); FMA2(cA[kk], xa[1], W0.y);
            FMA2(cA[kk], xa[2], W1.x); FMA2(cA[kk], xa[3], W1.y);
            FMA2(cA[kk], xa[4], W2.x); FMA2(cA[kk], xa[5], W2.y);
            FMA2(cA[kk], xa[6], W3.x); FMA2(cA[kk], xa[7], W3.y);
            FMA2(cB[kk], xb[0], W0.x); FMA2(cB[kk], xb[1], W0.y);
            FMA2(cB[kk], xb[2], W1.x); FMA2(cB[kk], xb[3], W1.y);
            FMA2(cB[kk], xb[4], W2.x); FMA2(cB[kk], xb[5], W2.y);
            FMA2(cB[kk], xb[6], W3.x); FMA2(cB[kk], xb[7], W3.y);
            FMA2(aA[kk], xa[0], G0.x); FMA2(aA[kk], xa[1], G0.y);
            FMA2(aA[kk], xa[2], G1.x); FMA2(aA[kk], xa[3], G1.y);
            FMA2(aA[kk], xa[4], G2.x); FMA2(aA[kk], xa[5], G2.y);
            FMA2(aA[kk], xa[6], G3.x); FMA2(aA[kk], xa[7], G3.y);
            FMA2(aB[kk], xb[0], G0.x); FMA2(aB[kk], xb[1], G0.y);
            FMA2(aB[kk], xb[2], G1.x); FMA2(aB[kk], xb[3], G1.y);
            FMA2(aB[kk], xb[4], G2.x); FMA2(aB[kk], xb[5], G2.y);
            FMA2(aB[kk], xb[6], G3.x); FMA2(aB[kk], xb[7], G3.y);
        }
    }

    // ---- epilogue: reduce once per k, tanh, d/s, penalties, gz += d.a ----
    float dA[8], dB[8];
    float dwA = 0.0f, dwB = 0.0f, swA = 0.0f, swB = 0.0f;
    float gzA = 0.0f, gzB = 0.0f, accI = 0.0f, accN = 0.0f;
#pragma unroll
    for (int kk = 0; kk < 8; kk++) {
        int k = kb + kk;
        float bk  = sm[OFF_B + k];
        float wyk = sm[OFF_WY + k];
        float wlt = sm[OFF_wlt + k];
        float wys = sm[OFF_wys + k];

        float cv = red2(cA[kk]) + bk;
        float av = red2(aA[kk]);
        float hv = yA * wyk;
        float w1 = cv + hv, w2 = cv - hv;
        float t1 = tanh_fast(w1), t2 = tanh_fast(w2);
        float dk = t1 - t2, sk = t1 + t2;
        dA[kk] = dk;
        SA[k]  = sk;
        gzA = fmaf(dk, av, gzA);
        dwA = fmaf(dk, wlt, dwA);
        swA = fmaf(sk, wys, swA);
        float e1 = fmaf(-t1, t1, 1.0f), e2 = fmaf(-t2, t2, 1.0f);
        accI = fmaf(e1, e1, accI);
        accI = fmaf(e2, e2, accI);
        float nt = fmaf(t2, w2, -(t1 * w1));
        accN = fmaf(nt, nt, accN);

        cv = red2(cB[kk]) + bk;
        av = red2(aB[kk]);
        hv = yB * wyk;
        w1 = cv + hv; w2 = cv - hv;
        t1 = tanh_fast(w1); t2 = tanh_fast(w2);
        dk = t1 - t2; sk = t1 + t2;
        dB[kk] = dk;
        SB[k]  = sk;
        gzB = fmaf(dk, av, gzB);
        dwB = fmaf(dk, wlt, dwB);
        swB = fmaf(sk, wys, swB);
        e1 = fmaf(-t1, t1, 1.0f); e2 = fmaf(-t2, t2, 1.0f);
        accI = fmaf(e1, e1, accI);
        accI = fmaf(e2, e2, accI);
        nt = fmaf(t2, w2, -(t1 * w1));
        accN = fmaf(nt, nt, accN);
    }

    __syncthreads();   // all s written

    // ---- Phase 2: gz += d^T M s — persistent packed accumulators ----
    unsigned long long mA[8], mB[8];
#pragma unroll
    for (int kk = 0; kk < 8; kk++) { mA[kk] = 0ULL; mB[kk] = 0ULL; }

#pragma unroll
    for (int qt = 0; qt < 4; qt++) {
        unsigned long long sa[8], sb[8];
#pragma unroll
        for (int j = 0; j < 8; j++) {
            sa[j] = packpair(SA[qt * 16 + 2 * j], SA[qt * 16 + 2 * j + 1]);
            sb[j] = packpair(SB[qt * 16 + 2 * j], SB[qt * 16 + 2 * j + 1]);
        }
#pragma unroll
        for (int kk = 0; kk < 8; kk++) {
            int k = kb + kk;
            const ulonglong2* pM = reinterpret_cast<const ulonglong2*>(sm + OFF_M + k * 64 + qt * 16);
            ulonglong2 M0 = pM[0], M1 = pM[1], M2 = pM[2], M3 = pM[3];
            FMA2(mA[kk], sa[0], M0.x); FMA2(mA[kk], sa[1], M0.y);
            FMA2(mA[kk], sa[2], M1.x); FMA2(mA[kk], sa[3], M1.y);
            FMA2(mA[kk], sa[4], M2.x); FMA2(mA[kk], sa[5], M2.y);
            FMA2(mA[kk], sa[6], M3.x); FMA2(mA[kk], sa[7], M3.y);
            FMA2(mB[kk], sb[0], M0.x); FMA2(mB[kk], sb[1], M0.y);
            FMA2(mB[kk], sb[2], M1.x); FMA2(mB[kk], sb[3], M1.y);
            FMA2(mB[kk], sb[4], M2.x); FMA2(mB[kk], sb[5], M2.y);
            FMA2(mB[kk], sb[6], M3.x); FMA2(mB[kk], sb[7], M3.y);
        }
    }
#pragma unroll
    for (int kk = 0; kk < 8; kk++) {
        gzA = fmaf(dA[kk], red2(mA[kk]), gzA);
        gzB = fmaf(dB[kk], red2(mB[kk]), gzB);
    }

    // ---- combine the 8 k-eighth warps ----
    if (q != 0) {
        int p = OFF_PART + (q - 1) * 256;
        sm[p + rA]       = gzA;  sm[p + rB]       = gzB;
        sm[p + 64 + rA]  = dwA;  sm[p + 64 + rB]  = dwB;
        sm[p + 128 + rA] = swA;  sm[p + 128 + rB] = swB;
        sm[p + 192 + rA] = xwA;  sm[p + 192 + rB] = xwB;
    }
    __syncthreads();
    if (q == 0) {
#pragma unroll
        for (int p = 0; p < 7; p++) {
            int b = OFF_PART + p * 256;
            gzA += sm[b + rA];       gzB += sm[b + rB];
            dwA += sm[b + 64 + rA];  dwB += sm[b + 64 + rB];
            swA += sm[b + 128 + rA]; swB += sm[b + 128 + rB];
            xwA += sm[b + 192 + rA]; xwB += sm[b + 192 + rB];
        }
        float wl64 = sm[OFF_MISC];
        out[row0 + rA] = 1.0f + 2.0f * yA * wl64 + dwA + 2.0f * yA * xwA + yA * swA + gzA;
        out[row0 + rB] = 1.0f + 2.0f * yB * wl64 + dwB + 2.0f * yB * xwB + yB * swB + gzB;
    }

    // ---- penalty reduction ----
#pragma unroll
    for (int off = 16; off > 0; off >>= 1) {
        accI += __shfl_xor_sync(0xffffffffu, accI, off);
        accN += __shfl_xor_sync(0xffffffffu, accN, off);
    }
    if (lane == 0) {
        sm[OFF_RED + q]     = accI;
        sm[OFF_RED + 8 + q] = accN;
    }
    __syncthreads();
    if (t == 0) {
        float pI = 0.0f, pN = 0.0f;
#pragma unroll
        for (int w = 0; w < 8; w++) { pI += sm[OFF_RED + w]; pN += sm[OFF_RED + 8 + w]; }
        gPartI[blockIdx.x] = pI;
        gPartN[blockIdx.x] = pN;
        __threadfence();
        unsigned int tk = atomicAdd(&gCount, 1u);
        sm[OFF_FLAG] = (tk == gridDim.x - 1) ? 1.0f : 0.0f;
    }
    __syncthreads();

    if (sm[OFF_FLAG] != 0.0f && t < 32) {
        __threadfence();
        double sI = 0.0, sN = 0.0;
        for (int i = t; i < (int)gridDim.x; i += 32) {
            sI += (double)gPartI[i];
            sN += (double)gPartN[i];
        }
#pragma unroll
        for (int off = 16; off > 0; off >>= 1) {
            sI += __shfl_xor_sync(0xffffffffu, sI, off);
            sN += __shfl_xor_sync(0xffffffffu, sN, off);
        }
        if (t == 0) {
            out[Bn]     = (float)(sI * (1.0 / 300.0));
            out[Bn + 1] = (float)sN;
            gCount = 0;   // reset for next graph replay
        }
    }
}

extern "C" void kernel_launch(void* const* d_in, const int* in_sizes, int n_in,
                              void* d_out, int out_size) {
    const float* inps = (const float*)d_in[0];
    const float* tw   = (const float*)d_in[1];
    const float* tb   = (const float*)d_in[2];
    const float* mw   = (const float*)d_in[3];
    float* out = (float*)d_out;

    int Bn = in_sizes[0] / 65;

    cudaFuncSetAttribute(fused_kernel,
                         cudaFuncAttributeMaxDynamicSharedMemorySize, SMEM_BYTES);

    prep_kernel<<<(PREP_FLOATS + 255) / 256, 256>>>(tw, tb, mw);
    fused_kernel<<<Bn / ROWS, THREADS, SMEM_BYTES>>>(inps, out, Bn);
}